// round 1
// baseline (speedup 1.0000x reference)
#include <cuda_runtime.h>
#include <cstdint>

// Problem constants (fixed by the dataset)
#define BB   8
#define CC   256
#define NN   16384      // H*W = 128*128
#define CK   256
#define CV   256
#define MSTK 512        // stacked M: rows 0..255 -> K (Wk), 256..511 -> V (Wv)

// Scratch (device-global; no allocations allowed)
__device__ float g_K[(size_t)BB * CK * NN];   // 128 MB
__device__ float g_V[(size_t)BB * CV * NN];   // 128 MB
__device__ float g_m[BB * CK];
__device__ float g_s[BB * CK];

// ---------------------------------------------------------------------------
// Packed f32x2 helpers (sm_100+): FFMA 3-reg is half-rate on B300 (rt_SMSP=2),
// fma.rn.f32x2 does 2 FMA per issue -> 2x fp32 throughput. ptxas never emits
// this from C++, so inline PTX.
// ---------------------------------------------------------------------------
__device__ __forceinline__ void fma2(unsigned long long& d,
                                     unsigned long long a,
                                     unsigned long long b) {
    asm("fma.rn.f32x2 %0, %1, %2, %0;" : "+l"(d) : "l"(a), "l"(b));
}
__device__ __forceinline__ unsigned long long pack_dup(float x) {
    unsigned long long r;
    asm("mov.b64 %0, {%1, %1};" : "=l"(r) : "f"(x));
    return r;
}
__device__ __forceinline__ float2 unpack2(unsigned long long v) {
    float2 p;
    asm("mov.b64 {%0, %1}, %2;" : "=f"(p.x), "=f"(p.y) : "l"(v));
    return p;
}

// ---------------------------------------------------------------------------
// K0: zero the output (poisoned to 0xAA; K3 accumulates with atomics)
// ---------------------------------------------------------------------------
__global__ void k0_zero(float* __restrict__ out, int n) {
    int i = blockIdx.x * 256 + threadIdx.x;
    if (i < n) out[i] = 0.0f;
}

// ---------------------------------------------------------------------------
// K1: stacked GEMM  [512 x 16384] = [512 x 256] @ [256 x 16384] per batch
//     rows 0..255 = Wk @ X + bk -> g_K, rows 256..511 = Wv @ X + bv -> g_V
// Tile 128x128, BK=8, 256 threads, 8x8 micro-tile via f32x2.
// grid (NN/128=128, MSTK/128=4, BB=8)
// ---------------------------------------------------------------------------
__global__ void __launch_bounds__(256)
k1_gemm(const float* __restrict__ x,
        const float* __restrict__ Wk, const float* __restrict__ bk,
        const float* __restrict__ Wv, const float* __restrict__ bv) {
    __shared__ float As[8][128];   // transposed: As[k][m]
    __shared__ float Bs[8][128];   // Bs[k][n]

    const int n0 = blockIdx.x * 128;
    const int m0 = blockIdx.y * 128;
    const int b  = blockIdx.z;
    const float* X = x + (size_t)b * CC * NN;

    const int tid = threadIdx.x;
    const int tx = tid & 15;       // 0..15 (n)
    const int ty = tid >> 4;       // 0..15 (m)

    // A loader: thread -> W row (m0 + tid/2), 4 cols at (tid&1)*4
    const int arow  = tid >> 1;            // 0..127
    const int acol4 = (tid & 1) * 4;
    const int gm = m0 + arow;              // 0..511
    const float* Wrow = (gm < CK) ? (Wk + (size_t)gm * CC)
                                  : (Wv + (size_t)(gm - CK) * CC);
    // B loader: thread -> X row (k0 + tid/32), 4 cols at (tid&31)*4
    const int brow = tid >> 5;             // 0..7
    const int bq   = (tid & 31) * 4;

    unsigned long long acc[8][4];
    #pragma unroll
    for (int i = 0; i < 8; ++i)
        #pragma unroll
        for (int j = 0; j < 4; ++j) acc[i][j] = 0ULL;

    for (int k0 = 0; k0 < CC; k0 += 8) {
        float4 av = *(const float4*)(Wrow + k0 + acol4);
        float4 bg = *(const float4*)(X + (size_t)(k0 + brow) * NN + n0 + bq);
        __syncthreads();
        As[acol4 + 0][arow] = av.x;
        As[acol4 + 1][arow] = av.y;
        As[acol4 + 2][arow] = av.z;
        As[acol4 + 3][arow] = av.w;
        *(float4*)&Bs[brow][bq] = bg;
        __syncthreads();

        #pragma unroll
        for (int kk = 0; kk < 8; ++kk) {
            float4 a0 = *(const float4*)&As[kk][ty * 8];
            float4 a1 = *(const float4*)&As[kk][ty * 8 + 4];
            const unsigned long long* bp =
                (const unsigned long long*)&Bs[kk][tx * 8];
            unsigned long long b2[4] = {bp[0], bp[1], bp[2], bp[3]};
            float avs[8] = {a0.x, a0.y, a0.z, a0.w, a1.x, a1.y, a1.z, a1.w};
            #pragma unroll
            for (int i = 0; i < 8; ++i) {
                unsigned long long ai = pack_dup(avs[i]);
                #pragma unroll
                for (int j = 0; j < 4; ++j) fma2(acc[i][j], ai, b2[j]);
            }
        }
    }

    // Write out with bias (branch uniform per CTA: m0 in {0,128,256,384})
    #pragma unroll
    for (int i = 0; i < 8; ++i) {
        const int m = m0 + ty * 8 + i;
        float bias;
        float* dst;
        if (m < CK) {
            bias = bk[m];
            dst = g_K + ((size_t)b * CK + m) * NN + n0 + tx * 8;
        } else {
            bias = bv[m - CK];
            dst = g_V + ((size_t)b * CV + (m - CK)) * NN + n0 + tx * 8;
        }
        float o[8];
        #pragma unroll
        for (int j = 0; j < 4; ++j) {
            float2 p = unpack2(acc[i][j]);
            o[2 * j]     = p.x + bias;
            o[2 * j + 1] = p.y + bias;
        }
        *(float4*)dst       = make_float4(o[0], o[1], o[2], o[3]);
        *(float4*)(dst + 4) = make_float4(o[4], o[5], o[6], o[7]);
    }
}

// ---------------------------------------------------------------------------
// K2: per (b,k) row of g_K: m = max_n, s = sum_n exp(K - m).
// One block per row (2048 blocks), 256 threads, float4 strided.
// ---------------------------------------------------------------------------
__global__ void __launch_bounds__(256) k2_rowstats() {
    const int row = blockIdx.x;            // b*256 + k
    const float4* K4 = (const float4*)(g_K + (size_t)row * NN);
    const int tid = threadIdx.x;
    __shared__ float red[256];

    float mx = -3.4e38f;
    for (int i = tid; i < NN / 4; i += 256) {
        float4 v = K4[i];
        mx = fmaxf(mx, fmaxf(fmaxf(v.x, v.y), fmaxf(v.z, v.w)));
    }
    red[tid] = mx;
    __syncthreads();
    for (int s = 128; s > 0; s >>= 1) {
        if (tid < s) red[tid] = fmaxf(red[tid], red[tid + s]);
        __syncthreads();
    }
    mx = red[0];
    __syncthreads();

    float sum = 0.0f;
    for (int i = tid; i < NN / 4; i += 256) {
        float4 v = K4[i];
        sum += __expf(v.x - mx) + __expf(v.y - mx) +
               __expf(v.z - mx) + __expf(v.w - mx);
    }
    red[tid] = sum;
    __syncthreads();
    for (int s = 128; s > 0; s >>= 1) {
        if (tid < s) red[tid] += red[tid + s];
        __syncthreads();
    }
    if (tid == 0) {
        g_m[row] = mx;
        g_s[row] = red[0];
    }
}

// ---------------------------------------------------------------------------
// K3: context[b,k,v] = (1/s[b,k]) * sum_n exp(K[b,k,n]-m[b,k]) * V[b,v,n]
// Split over N: 16 chunks of 1024. Output tile 128x128, atomicAdd of
// row-scaled partials. grid (4 tiles, 16 chunks, 8 batches), 256 threads.
// ---------------------------------------------------------------------------
__global__ void __launch_bounds__(256)
k3_context(float* __restrict__ out) {
    __shared__ float As[8][128];   // As[n_local][k_row] = exp(K - m)
    __shared__ float Bs[8][128];   // Bs[n_local][v_row] = V

    const int km0   = (blockIdx.x & 1) * 128;
    const int vm0   = (blockIdx.x >> 1) * 128;
    const int nbase = blockIdx.y * 1024;
    const int b     = blockIdx.z;

    const int tid = threadIdx.x;
    const int tx = tid & 15;
    const int ty = tid >> 4;

    const int r     = tid >> 1;            // 0..127
    const int half4 = (tid & 1) * 4;
    const float* Krow = g_K + ((size_t)b * CK + km0 + r) * NN;
    const float* Vrow = g_V + ((size_t)b * CV + vm0 + r) * NN;
    const float mrow = g_m[b * CK + km0 + r];

    unsigned long long acc[8][4];
    #pragma unroll
    for (int i = 0; i < 8; ++i)
        #pragma unroll
        for (int j = 0; j < 4; ++j) acc[i][j] = 0ULL;

    for (int n = nbase; n < nbase + 1024; n += 8) {
        float4 a = *(const float4*)(Krow + n + half4);
        float4 v = *(const float4*)(Vrow + n + half4);
        __syncthreads();
        As[half4 + 0][r] = __expf(a.x - mrow);
        As[half4 + 1][r] = __expf(a.y - mrow);
        As[half4 + 2][r] = __expf(a.z - mrow);
        As[half4 + 3][r] = __expf(a.w - mrow);
        Bs[half4 + 0][r] = v.x;
        Bs[half4 + 1][r] = v.y;
        Bs[half4 + 2][r] = v.z;
        Bs[half4 + 3][r] = v.w;
        __syncthreads();

        #pragma unroll
        for (int kk = 0; kk < 8; ++kk) {
            float4 a0 = *(const float4*)&As[kk][ty * 8];
            float4 a1 = *(const float4*)&As[kk][ty * 8 + 4];
            const unsigned long long* bp =
                (const unsigned long long*)&Bs[kk][tx * 8];
            unsigned long long b2[4] = {bp[0], bp[1], bp[2], bp[3]};
            float avs[8] = {a0.x, a0.y, a0.z, a0.w, a1.x, a1.y, a1.z, a1.w};
            #pragma unroll
            for (int i = 0; i < 8; ++i) {
                unsigned long long ai = pack_dup(avs[i]);
                #pragma unroll
                for (int j = 0; j < 4; ++j) fma2(acc[i][j], ai, b2[j]);
            }
        }
    }

    // Scale by 1/s per k-row and accumulate into out[b, k, v].
    float invs[8];
    #pragma unroll
    for (int i = 0; i < 8; ++i)
        invs[i] = 1.0f / g_s[b * CK + km0 + ty * 8 + i];

    #pragma unroll
    for (int i = 0; i < 8; ++i) {
        const size_t base =
            ((size_t)b * CK + km0 + ty * 8 + i) * CV + vm0 + tx * 8;
        #pragma unroll
        for (int j = 0; j < 4; ++j) {
            float2 p = unpack2(acc[i][j]);
            atomicAdd(out + base + 2 * j,     p.x * invs[i]);
            atomicAdd(out + base + 2 * j + 1, p.y * invs[i]);
        }
    }
}

// ---------------------------------------------------------------------------
// Launch: x, Wk, bk, Wv, bv -> out [8,256,256] fp32
// ---------------------------------------------------------------------------
extern "C" void kernel_launch(void* const* d_in, const int* in_sizes, int n_in,
                              void* d_out, int out_size) {
    const float* x  = (const float*)d_in[0];
    const float* Wk = (const float*)d_in[1];
    const float* bk = (const float*)d_in[2];
    const float* Wv = (const float*)d_in[3];
    const float* bv = (const float*)d_in[4];
    float* out = (float*)d_out;

    k0_zero<<<(out_size + 255) / 256, 256>>>(out, out_size);

    dim3 g1(NN / 128, MSTK / 128, BB);
    k1_gemm<<<g1, 256>>>(x, Wk, bk, Wv, bv);

    k2_rowstats<<<BB * CK, 256>>>();

    dim3 g3(4, 16, BB);
    k3_context<<<g3, 256>>>(out);
}

// round 4
// speedup vs baseline: 3.1384x; 3.1384x over previous
#include <cuda_runtime.h>
#include <cstdint>

#define BB   8
#define CC   256
#define NN   16384
#define CK   256
#define CV   256

// Scratch (device-global; no allocations allowed)
__device__ float g_K[(size_t)BB * CK * NN];   // 128 MB (holds exp(K + bk))
__device__ float g_V[(size_t)BB * CV * NN];   // 128 MB (V + bv)
__device__ float g_s[BB * CK];                // softmax denominators

// ---------------------------------------------------------------------------
// tf32 helpers (mma.sync path: works on plain sm_103 virtual arch)
// ---------------------------------------------------------------------------
__device__ __forceinline__ float to_tf32(float x) {
    uint32_t u;
    asm("cvt.rna.tf32.f32 %0, %1;" : "=r"(u) : "f"(x));
    return __uint_as_float(u);
}

__device__ __forceinline__ void mma_tf32(float* d, const uint32_t* a,
                                         const uint32_t* b) {
    asm volatile(
        "mma.sync.aligned.m16n8k8.row.col.f32.tf32.tf32.f32 "
        "{%0,%1,%2,%3}, {%4,%5,%6,%7}, {%8,%9}, {%0,%1,%2,%3};"
        : "+f"(d[0]), "+f"(d[1]), "+f"(d[2]), "+f"(d[3])
        : "r"(a[0]), "r"(a[1]), "r"(a[2]), "r"(a[3]), "r"(b[0]), "r"(b[1]));
}

#define SMS 36   // smem row stride in floats (conflict-free: (row*4+col)%32)

// ---------------------------------------------------------------------------
// K0: zero output and g_s
// ---------------------------------------------------------------------------
__global__ void k0_zero(float* __restrict__ out, int n) {
    int i = blockIdx.x * 256 + threadIdx.x;
    if (i < n) out[i] = 0.0f;
    if (i < BB * CK) g_s[i] = 0.0f;
}

// ---------------------------------------------------------------------------
// K1: (K|V)[m, n] = W[m, :] @ x[:, n] + bias, then K-tiles: exp + rowsum.
// CTA tile 128x128, contraction CC in 8 chunks of 32. 256 thr = 8 warps
// (4 m x 2 n), warp tile 32x64, tf32 mma.sync m16n8k8.
// grid (4 m-tiles [0,1->K; 2,3->V], 128 n-tiles, 8 b)
// ---------------------------------------------------------------------------
__global__ void __launch_bounds__(256, 2)
k1_gemm(const float* __restrict__ x,
        const float* __restrict__ Wk, const float* __restrict__ bk,
        const float* __restrict__ Wv, const float* __restrict__ bv) {
    __shared__ float smA[128 * SMS];
    __shared__ float smB[128 * SMS];

    const int tid  = threadIdx.x;
    const int wid  = tid >> 5;
    const int lane = tid & 31;
    const int lr   = lane >> 2;       // 0..7
    const int lc   = lane & 3;        // 0..3
    const int mw   = (wid & 3) * 32;  // warp m offset
    const int nw   = (wid >> 2) * 64; // warp n offset

    const int mtile = blockIdx.x;     // 0..3
    const int n0    = blockIdx.y * 128;
    const int b     = blockIdx.z;
    const bool isK  = (mtile < 2);
    const int mrow0 = (mtile & 1) * 128;

    const float* Wbase = isK ? Wk : Wv;
    const float* bias  = isK ? bk : bv;
    const float* X = x + (size_t)b * CC * NN + n0;

    float acc[2][8][4];
    #pragma unroll
    for (int i = 0; i < 2; ++i)
        #pragma unroll
        for (int j = 0; j < 8; ++j)
            #pragma unroll
            for (int t = 0; t < 4; ++t) acc[i][j][t] = 0.0f;

    const int bw4 = 4 * wid;          // B loader: 4 channels per warp

    for (int ic = 0; ic < 8; ++ic) {
        const int c0 = ic * 32;
        // A = W tile [128 m][32 c], K-major direct. 4 passes x 256 thr x float4.
        #pragma unroll
        for (int r = 0; r < 4; ++r) {
            const int idx = tid + r * 256;
            const int row = idx >> 3;
            const int q   = (idx & 7) * 4;
            float4 v = *(const float4*)(Wbase + (size_t)(mrow0 + row) * CC + c0 + q);
            float* d = &smA[row * SMS + q];
            d[0] = to_tf32(v.x); d[1] = to_tf32(v.y);
            d[2] = to_tf32(v.z); d[3] = to_tf32(v.w);
        }
        // B = x^T tile [128 n][32 c]: gather 4 channels (coalesced over n)
        {
            const float* Xc = X + (size_t)(c0 + bw4) * NN;
            #pragma unroll
            for (int i2 = 0; i2 < 4; ++i2) {
                int nl = i2 * 32 + lane;
                float* d = &smB[nl * SMS + bw4];
                d[0] = to_tf32(Xc[nl]);
                d[1] = to_tf32(Xc[(size_t)NN + nl]);
                d[2] = to_tf32(Xc[(size_t)2 * NN + nl]);
                d[3] = to_tf32(Xc[(size_t)3 * NN + nl]);
            }
        }
        __syncthreads();

        #pragma unroll
        for (int ks = 0; ks < 4; ++ks) {
            const int kc = ks * 8;
            uint32_t a[2][4], bf[8][2];
            #pragma unroll
            for (int i = 0; i < 2; ++i) {
                const float* p0 = &smA[(mw + i * 16 + lr) * SMS + kc + lc];
                const float* p1 = p0 + 8 * SMS;
                a[i][0] = __float_as_uint(p0[0]);
                a[i][1] = __float_as_uint(p1[0]);
                a[i][2] = __float_as_uint(p0[4]);
                a[i][3] = __float_as_uint(p1[4]);
            }
            #pragma unroll
            for (int j = 0; j < 8; ++j) {
                const float* p = &smB[(nw + j * 8 + lr) * SMS + kc + lc];
                bf[j][0] = __float_as_uint(p[0]);
                bf[j][1] = __float_as_uint(p[4]);
            }
            #pragma unroll
            for (int i = 0; i < 2; ++i)
                #pragma unroll
                for (int j = 0; j < 8; ++j) mma_tf32(acc[i][j], a[i], bf[j]);
        }
        __syncthreads();
    }

    // Epilogue. rows per thread: i in {0,1} x {lr, lr+8}; cols: j*8 + 2*lc.
    float* gout = isK ? g_K : g_V;
    float rs[2][2] = {{0.f, 0.f}, {0.f, 0.f}};
    #pragma unroll
    for (int i = 0; i < 2; ++i) {
        const int ch0 = mrow0 + mw + i * 16 + lr;        // row of d0,d1
        const int ch1 = ch0 + 8;                         // row of d2,d3
        const float b0 = bias[ch0], b1 = bias[ch1];
        float* r0 = gout + ((size_t)b * 256 + ch0) * NN + n0 + nw + 2 * lc;
        float* r1 = gout + ((size_t)b * 256 + ch1) * NN + n0 + nw + 2 * lc;
        #pragma unroll
        for (int j = 0; j < 8; ++j) {
            float v0 = acc[i][j][0] + b0, v1 = acc[i][j][1] + b0;
            float v2 = acc[i][j][2] + b1, v3 = acc[i][j][3] + b1;
            if (isK) {
                v0 = __expf(v0); v1 = __expf(v1);
                v2 = __expf(v2); v3 = __expf(v3);
                rs[i][0] += v0 + v1;
                rs[i][1] += v2 + v3;
            }
            *(float2*)(r0 + j * 8) = make_float2(v0, v1);
            *(float2*)(r1 + j * 8) = make_float2(v2, v3);
        }
    }
    if (isK) {
        #pragma unroll
        for (int i = 0; i < 2; ++i)
            #pragma unroll
            for (int h = 0; h < 2; ++h) {
                float v = rs[i][h];
                v += __shfl_xor_sync(0xffffffffu, v, 1);
                v += __shfl_xor_sync(0xffffffffu, v, 2);
                if (lc == 0) {
                    int ch = mrow0 + mw + i * 16 + lr + h * 8;
                    atomicAdd(&g_s[b * 256 + ch], v);
                }
            }
    }
}

// ---------------------------------------------------------------------------
// K3: context[b,k,v] = (1/s[b,k]) * sum_n expK[b,k,n] * V[b,v,n]
// Same MMA structure; contraction n split 16 ways (1024 each, 32 chunks).
// grid (4 output tiles, 16 splits, 8 b); atomicAdd into out.
// ---------------------------------------------------------------------------
__global__ void __launch_bounds__(256, 2)
k3_context(float* __restrict__ out) {
    __shared__ float smA[128 * SMS];
    __shared__ float smB[128 * SMS];

    const int tid  = threadIdx.x;
    const int wid  = tid >> 5;
    const int lane = tid & 31;
    const int lr   = lane >> 2;
    const int lc   = lane & 3;
    const int mw   = (wid & 3) * 32;
    const int nw   = (wid >> 2) * 64;

    const int km0 = (blockIdx.x & 1) * 128;
    const int vm0 = (blockIdx.x >> 1) * 128;
    const int nb  = blockIdx.y * 1024;
    const int b   = blockIdx.z;

    const float* Kbase = g_K + ((size_t)b * 256 + km0) * NN + nb;
    const float* Vbase = g_V + ((size_t)b * 256 + vm0) * NN + nb;

    float acc[2][8][4];
    #pragma unroll
    for (int i = 0; i < 2; ++i)
        #pragma unroll
        for (int j = 0; j < 8; ++j)
            #pragma unroll
            for (int t = 0; t < 4; ++t) acc[i][j][t] = 0.0f;

    for (int ic = 0; ic < 32; ++ic) {
        const int c0 = ic * 32;
        // Both tiles [128 rows][32 n-local]: 4 passes x 256 thr x float4 each.
        #pragma unroll
        for (int r = 0; r < 4; ++r) {
            const int idx = tid + r * 256;
            const int row = idx >> 3;
            const int q   = (idx & 7) * 4;
            float4 va = *(const float4*)(Kbase + (size_t)row * NN + c0 + q);
            float* d = &smA[row * SMS + q];
            d[0] = to_tf32(va.x); d[1] = to_tf32(va.y);
            d[2] = to_tf32(va.z); d[3] = to_tf32(va.w);
            float4 vb = *(const float4*)(Vbase + (size_t)row * NN + c0 + q);
            float* e = &smB[row * SMS + q];
            e[0] = to_tf32(vb.x); e[1] = to_tf32(vb.y);
            e[2] = to_tf32(vb.z); e[3] = to_tf32(vb.w);
        }
        __syncthreads();

        #pragma unroll
        for (int ks = 0; ks < 4; ++ks) {
            const int kc = ks * 8;
            uint32_t a[2][4], bf[8][2];
            #pragma unroll
            for (int i = 0; i < 2; ++i) {
                const float* p0 = &smA[(mw + i * 16 + lr) * SMS + kc + lc];
                const float* p1 = p0 + 8 * SMS;
                a[i][0] = __float_as_uint(p0[0]);
                a[i][1] = __float_as_uint(p1[0]);
                a[i][2] = __float_as_uint(p0[4]);
                a[i][3] = __float_as_uint(p1[4]);
            }
            #pragma unroll
            for (int j = 0; j < 8; ++j) {
                const float* p = &smB[(nw + j * 8 + lr) * SMS + kc + lc];
                bf[j][0] = __float_as_uint(p[0]);
                bf[j][1] = __float_as_uint(p[4]);
            }
            #pragma unroll
            for (int i = 0; i < 2; ++i)
                #pragma unroll
                for (int j = 0; j < 8; ++j) mma_tf32(acc[i][j], a[i], bf[j]);
        }
        __syncthreads();
    }

    #pragma unroll
    for (int i = 0; i < 2; ++i) {
        const int k0r = km0 + mw + i * 16 + lr;
        const int k1r = k0r + 8;
        const float inv0 = 1.0f / g_s[b * 256 + k0r];
        const float inv1 = 1.0f / g_s[b * 256 + k1r];
        float* r0 = out + ((size_t)b * 256 + k0r) * 256 + vm0 + nw + 2 * lc;
        float* r1 = out + ((size_t)b * 256 + k1r) * 256 + vm0 + nw + 2 * lc;
        #pragma unroll
        for (int j = 0; j < 8; ++j) {
            atomicAdd(r0 + j * 8,     acc[i][j][0] * inv0);
            atomicAdd(r0 + j * 8 + 1, acc[i][j][1] * inv0);
            atomicAdd(r1 + j * 8,     acc[i][j][2] * inv1);
            atomicAdd(r1 + j * 8 + 1, acc[i][j][3] * inv1);
        }
    }
}

// ---------------------------------------------------------------------------
// Launch
// ---------------------------------------------------------------------------
extern "C" void kernel_launch(void* const* d_in, const int* in_sizes, int n_in,
                              void* d_out, int out_size) {
    const float* x  = (const float*)d_in[0];
    const float* Wk = (const float*)d_in[1];
    const float* bk = (const float*)d_in[2];
    const float* Wv = (const float*)d_in[3];
    const float* bv = (const float*)d_in[4];
    float* out = (float*)d_out;

    k0_zero<<<(out_size + 255) / 256, 256>>>(out, out_size);

    dim3 g1(4, 128, BB);
    k1_gemm<<<g1, 256>>>(x, Wk, bk, Wv, bv);

    dim3 g3(4, 16, BB);
    k3_context<<<g3, 256>>>(out);
}